// round 3
// baseline (speedup 1.0000x reference)
#include <cuda_runtime.h>

#define FEAT 32
#define RES_H 512
#define RES_W 128
#define HW (RES_H * RES_W)
#define PLANE_ELEMS (FEAT * HW)
#define TIME_STEP_F 0.00390625f   /* 1/(2*128), exact in fp32 */
#define INV_BOUNDS_F 0.625f       /* fp32(1/fp32(1.6)) == 0.625 exactly; XLA folds x/1.6 -> x*0.625 */

// 3 transposed planes, layout [H][W][F] so 32 features are contiguous (128B line).
// 3 * 2,097,152 * 4B = 25.2 MB device scratch (static, allowed).
__device__ float g_tp[3][PLANE_ELEMS];

// ---------------------------------------------------------------------------
// Pre-pass: transpose each plane [F=32, HW=65536] -> [HW, F] via smem tiles.
// Reads coalesced along HW, writes coalesced along F.
// ---------------------------------------------------------------------------
__global__ void transpose_planes(const float* __restrict__ p0,
                                 const float* __restrict__ p1,
                                 const float* __restrict__ p2) {
    __shared__ float tile[32][33];   // +1 pad: conflict-free transpose
    const int plane = blockIdx.y;
    const float* __restrict__ src = (plane == 0) ? p0 : ((plane == 1) ? p1 : p2);
    float* __restrict__ dst = g_tp[plane];

    const int hw0 = blockIdx.x * 32;
    const int x = threadIdx.x;   // hw within tile on load; feature on store
    const int y = threadIdx.y;   // 0..7

    #pragma unroll
    for (int fy = y; fy < 32; fy += 8)
        tile[fy][x] = src[fy * HW + hw0 + x];
    __syncthreads();
    #pragma unroll
    for (int r = y; r < 32; r += 8)
        dst[(hw0 + r) * FEAT + x] = tile[x][r];
}

// ---------------------------------------------------------------------------
// Index math — matches XLA's folded lowering:
//   v = (c + 1) * 63.5   (W axis; 0.5*(128-1) folded, exact fp32)
//   v = (c + 1) * 255.5  (H axis; 0.5*(512-1) folded, exact fp32)
// round half-to-even (rintf == jnp.round), cast, clip.
// Explicit __fadd_rn/__fmul_rn prevent nvcc FMA contraction (XLA keeps
// add and mul as separate rounded HLO ops).
// ---------------------------------------------------------------------------
__device__ __forceinline__ int idx_w(float c) {
    float v = __fmul_rn(__fadd_rn(c, 1.0f), 63.5f);
    int k = (int)rintf(v);
    return min(max(k, 0), RES_W - 1);
}
__device__ __forceinline__ int idx_h(float c) {
    float v = __fmul_rn(__fadd_rn(c, 1.0f), 255.5f);
    int k = (int)rintf(v);
    return min(max(k, 0), RES_H - 1);
}

// ---------------------------------------------------------------------------
// Main kernel: one warp per point, lane = feature.
// feat[i,f] = tp0[iy0,ix,f] * tp1[iy1,ix,f] * tp2[iy2,ix,f]
// Only the LAST point computes the shifted variant + scalar cond select.
// out layout: [feature_A (N*32)] then [feature_B (N*32)].
// ---------------------------------------------------------------------------
__global__ void displacement_kernel(const float* __restrict__ pts,
                                    const float* __restrict__ tim,
                                    float* __restrict__ out,
                                    int n) {
    const long long gtid = (long long)blockIdx.x * blockDim.x + threadIdx.x;
    const int i = (int)(gtid >> 5);
    const int f = (int)(gtid & 31);
    if (i >= n) return;

    // Broadcast loads (all lanes of the warp hit the same addresses).
    const float t  = __fadd_rn(__fmul_rn(tim[i], 2.0f), -1.0f);
    const float p0 = __fmul_rn(-pts[3 * i + 0], INV_BOUNDS_F);
    const float p1 = __fmul_rn(-pts[3 * i + 1], INV_BOUNDS_F);
    const float p2 = __fmul_rn(-pts[3 * i + 2], INV_BOUNDS_F);

    const int ix = idx_w(t);
    const int b0 = (idx_h(p0) * RES_W + ix) * FEAT + f;
    const int b1 = (idx_h(p1) * RES_W + ix) * FEAT + f;
    const int b2 = (idx_h(p2) * RES_W + ix) * FEAT + f;

    const float feat = __fmul_rn(__fmul_rn(__ldg(&g_tp[0][b0]),
                                           __ldg(&g_tp[1][b1])),
                                 __ldg(&g_tp[2][b2]));

    float fa = feat, fb = feat;
    if (i == n - 1) {
        // data.at[-1].add(-TIME_STEP): ALL 4 coords of the last row shift.
        const float ts = __fadd_rn(t,  -TIME_STEP_F);
        const float q0 = __fadd_rn(p0, -TIME_STEP_F);
        const float q1 = __fadd_rn(p1, -TIME_STEP_F);
        const float q2 = __fadd_rn(p2, -TIME_STEP_F);
        const int ixs = idx_w(ts);
        const int s0 = (idx_h(q0) * RES_W + ixs) * FEAT + f;
        const int s1 = (idx_h(q1) * RES_W + ixs) * FEAT + f;
        const int s2 = (idx_h(q2) * RES_W + ixs) * FEAT + f;
        const float fshift = __fmul_rn(__fmul_rn(__ldg(&g_tp[0][s0]),
                                                 __ldg(&g_tp[1][s1])),
                                       __ldg(&g_tp[2][s2]));
        // cond = data[-1,0] + TIME_STEP > 1.0  (scalar; data[-1,0] == p0 here)
        const bool cond = __fadd_rn(p0, TIME_STEP_F) > 1.0f;
        fa = cond ? fshift : feat;
        fb = cond ? feat   : fshift;
    }

    out[gtid] = fa;                           // feature_A[i, f]
    out[(long long)n * FEAT + gtid] = fb;     // feature_B[i, f]
}

extern "C" void kernel_launch(void* const* d_in, const int* in_sizes, int n_in,
                              void* d_out, int out_size) {
    const float* pts    = (const float*)d_in[0];
    const float* tim    = (const float*)d_in[1];
    const float* plane0 = (const float*)d_in[2];
    const float* plane1 = (const float*)d_in[3];
    const float* plane2 = (const float*)d_in[4];
    float* out = (float*)d_out;

    const int n = in_sizes[0] / 3;   // pts is [N,3]

    // 1) Transpose planes into [H,W,F] scratch (coalesced both sides).
    dim3 tb(32, 8);
    dim3 tg(HW / 32, 3);
    transpose_planes<<<tg, tb>>>(plane0, plane1, plane2);

    // 2) Warp-per-point gather + product + dual store.
    const long long total = (long long)n * FEAT;
    const int block = 256;
    const long long grid = (total + block - 1) / block;
    displacement_kernel<<<(unsigned int)grid, block>>>(pts, tim, out, n);
}

// round 4
// speedup vs baseline: 1.8252x; 1.8252x over previous
#include <cuda_runtime.h>

#define FEAT 32
#define RES_H 512
#define RES_W 128
#define HW (RES_H * RES_W)
#define PLANE_ELEMS (FEAT * HW)
#define TIME_STEP_F 0.00390625f   /* 1/(2*128), exact in fp32 */
#define INV_BOUNDS_F 0.625f       /* fp32(1/fp32(1.6)) == 0.625 exactly (XLA folds /1.6 -> *0.625) */
#define PPW 8                     /* points per warp */

// 3 transposed planes, layout [H][W][F]: 32 features contiguous (one 128B line).
__device__ float g_tp[3][PLANE_ELEMS];

// ---------------------------------------------------------------------------
// Pre-pass: transpose each plane [F=32, HW=65536] -> [HW, F].
// ---------------------------------------------------------------------------
__global__ void transpose_planes(const float* __restrict__ p0,
                                 const float* __restrict__ p1,
                                 const float* __restrict__ p2) {
    __shared__ float tile[32][33];
    const int plane = blockIdx.y;
    const float* __restrict__ src = (plane == 0) ? p0 : ((plane == 1) ? p1 : p2);
    float* __restrict__ dst = g_tp[plane];

    const int hw0 = blockIdx.x * 32;
    const int x = threadIdx.x;
    const int y = threadIdx.y;

    #pragma unroll
    for (int fy = y; fy < 32; fy += 8)
        tile[fy][x] = src[fy * HW + hw0 + x];
    __syncthreads();
    #pragma unroll
    for (int r = y; r < 32; r += 8)
        dst[(hw0 + r) * FEAT + x] = tile[x][r];
}

// ---------------------------------------------------------------------------
// Index math — XLA-folded forms, round half-to-even, clamp. No FMA contraction.
// ---------------------------------------------------------------------------
__device__ __forceinline__ int idx_w(float c) {
    float v = __fmul_rn(__fadd_rn(c, 1.0f), 63.5f);     // 0.5*(128-1) folded
    int k = (int)rintf(v);
    return min(max(k, 0), RES_W - 1);
}
__device__ __forceinline__ int idx_h(float c) {
    float v = __fmul_rn(__fadd_rn(c, 1.0f), 255.5f);    // 0.5*(512-1) folded
    int k = (int)rintf(v);
    return min(max(k, 0), RES_H - 1);
}

// ---------------------------------------------------------------------------
// Main kernel: each warp processes PPW=8 points.
// Phase 1: lanes 0..7 compute base offsets for one point each (amortizes the
//          scalar math: issued once per 8 points instead of once per point).
// Phase 2: unrolled loop; shfl-broadcast offsets, 3 coalesced 128B gathers,
//          product, 2 coalesced 128B stores. ~14 warp-instr per point.
// ---------------------------------------------------------------------------
__global__ void displacement_kernel(const float* __restrict__ pts,
                                    const float* __restrict__ tim,
                                    float* __restrict__ out,
                                    int n) {
    const int warp_id = blockIdx.x * (blockDim.x >> 5) + (threadIdx.x >> 5);
    const int lane = threadIdx.x & 31;
    const int base = warp_id * PPW;
    if (base >= n) return;

    // Phase 1 (lanes 0..7 active)
    float t = 0.f, p0 = 0.f, p1 = 0.f, p2 = 0.f;
    int b0 = 0, b1 = 0, b2 = 0;
    const int li = base + lane;
    if (lane < PPW && li < n) {
        t  = __fadd_rn(__fmul_rn(tim[li], 2.0f), -1.0f);
        p0 = __fmul_rn(-pts[3 * li + 0], INV_BOUNDS_F);
        p1 = __fmul_rn(-pts[3 * li + 1], INV_BOUNDS_F);
        p2 = __fmul_rn(-pts[3 * li + 2], INV_BOUNDS_F);
        const int ix = idx_w(t);
        b0 = (idx_h(p0) * RES_W + ix) * FEAT;
        b1 = (idx_h(p1) * RES_W + ix) * FEAT;
        b2 = (idx_h(p2) * RES_W + ix) * FEAT;
    }

    const long long nb = (long long)n * FEAT;

    // Phase 2
    #pragma unroll
    for (int j = 0; j < PPW; j++) {
        const int i = base + j;
        if (i >= n) break;
        const int o0 = __shfl_sync(0xffffffffu, b0, j) + lane;
        const int o1 = __shfl_sync(0xffffffffu, b1, j) + lane;
        const int o2 = __shfl_sync(0xffffffffu, b2, j) + lane;

        const float v = __fmul_rn(__fmul_rn(__ldg(&g_tp[0][o0]),
                                            __ldg(&g_tp[1][o1])),
                                  __ldg(&g_tp[2][o2]));

        float fa = v, fb = v;
        if (i == n - 1) {
            // data.at[-1].add(-TIME_STEP): all 4 coords of the LAST row shift.
            const float lt  = __shfl_sync(0xffffffffu, t,  j);
            const float lp0 = __shfl_sync(0xffffffffu, p0, j);
            const float lp1 = __shfl_sync(0xffffffffu, p1, j);
            const float lp2 = __shfl_sync(0xffffffffu, p2, j);
            const float ts = __fadd_rn(lt,  -TIME_STEP_F);
            const float q0 = __fadd_rn(lp0, -TIME_STEP_F);
            const float q1 = __fadd_rn(lp1, -TIME_STEP_F);
            const float q2 = __fadd_rn(lp2, -TIME_STEP_F);
            const int ixs = idx_w(ts);
            const int s0 = (idx_h(q0) * RES_W + ixs) * FEAT + lane;
            const int s1 = (idx_h(q1) * RES_W + ixs) * FEAT + lane;
            const int s2 = (idx_h(q2) * RES_W + ixs) * FEAT + lane;
            const float fshift = __fmul_rn(__fmul_rn(__ldg(&g_tp[0][s0]),
                                                     __ldg(&g_tp[1][s1])),
                                           __ldg(&g_tp[2][s2]));
            const bool cond = __fadd_rn(lp0, TIME_STEP_F) > 1.0f;
            fa = cond ? fshift : v;
            fb = cond ? v      : fshift;
        }

        out[(long long)i * FEAT + lane] = fa;        // feature_A[i, lane]
        out[nb + (long long)i * FEAT + lane] = fb;   // feature_B[i, lane]
    }
}

extern "C" void kernel_launch(void* const* d_in, const int* in_sizes, int n_in,
                              void* d_out, int out_size) {
    const float* pts    = (const float*)d_in[0];
    const float* tim    = (const float*)d_in[1];
    const float* plane0 = (const float*)d_in[2];
    const float* plane1 = (const float*)d_in[3];
    const float* plane2 = (const float*)d_in[4];
    float* out = (float*)d_out;

    const int n = in_sizes[0] / 3;   // pts is [N,3]

    // 1) Transpose planes into [H,W,F] scratch.
    dim3 tb(32, 8);
    dim3 tg(HW / 32, 3);
    transpose_planes<<<tg, tb>>>(plane0, plane1, plane2);

    // 2) Warp-per-8-points gather + product + dual store.
    const int block = 256;                       // 8 warps
    const int pts_per_block = (block / 32) * PPW; // 64
    const int grid = (n + pts_per_block - 1) / pts_per_block;
    displacement_kernel<<<grid, block>>>(pts, tim, out, n);
}

// round 5
// speedup vs baseline: 1.9034x; 1.0428x over previous
#include <cuda_runtime.h>

#define FEAT 32
#define RES_H 512
#define RES_W 128
#define HW (RES_H * RES_W)
#define PLANE_ELEMS (FEAT * HW)
#define TIME_STEP_F 0.00390625f   /* 1/(2*128), exact in fp32 */
#define INV_BOUNDS_F 0.625f       /* fp32(1/fp32(1.6)) == 0.625 exactly (XLA folds /1.6 -> *0.625) */
#define PPW 16                    /* points per warp */

// 3 transposed planes, layout [H][W][F]: 32 features contiguous (one 128B line).
__device__ float g_tp[3][PLANE_ELEMS];

// ---------------------------------------------------------------------------
// Packed f32 pair multiply (sm_103a). IEEE rn per element — bit-identical to
// two scalar __fmul_rn.
// ---------------------------------------------------------------------------
__device__ __forceinline__ unsigned long long mul2(unsigned long long a,
                                                   unsigned long long b) {
    unsigned long long r;
    asm("mul.rn.f32x2 %0, %1, %2;" : "=l"(r) : "l"(a), "l"(b));
    return r;
}

// ---------------------------------------------------------------------------
// Pre-pass: transpose each plane [F=32, HW] -> [HW, F], float4 on both
// global sides. Tile: 32 features x 128 hw per block (256 threads).
// ---------------------------------------------------------------------------
__global__ void transpose_planes(const float* __restrict__ p0,
                                 const float* __restrict__ p1,
                                 const float* __restrict__ p2) {
    __shared__ float tile[128][33];     // [hw][f], +1 pad
    const int plane = blockIdx.y;
    const float* __restrict__ src = (plane == 0) ? p0 : ((plane == 1) ? p1 : p2);
    float* __restrict__ dst = g_tp[plane];

    const int hw0 = blockIdx.x * 128;
    const int tid = threadIdx.x;

    #pragma unroll
    for (int k = 0; k < 4; k++) {
        const int lin = tid + 256 * k;      // 0..1023
        const int f  = lin >> 5;            // 0..31
        const int vc = lin & 31;            // 0..31 (float4 column)
        const float4 v = *(const float4*)&src[f * HW + hw0 + vc * 4];
        tile[vc * 4 + 0][f] = v.x;
        tile[vc * 4 + 1][f] = v.y;
        tile[vc * 4 + 2][f] = v.z;
        tile[vc * 4 + 3][f] = v.w;
    }
    __syncthreads();
    #pragma unroll
    for (int k = 0; k < 4; k++) {
        const int lin = tid + 256 * k;      // 0..1023
        const int r  = lin >> 3;            // 0..127 (hw row)
        const int fc = lin & 7;             // float4 chunk of features
        float4 w;
        w.x = tile[r][fc * 4 + 0];
        w.y = tile[r][fc * 4 + 1];
        w.z = tile[r][fc * 4 + 2];
        w.w = tile[r][fc * 4 + 3];
        *(float4*)&dst[(hw0 + r) * FEAT + fc * 4] = w;
    }
}

// ---------------------------------------------------------------------------
// Index math — XLA-folded forms, round half-to-even, clamp. No FMA contraction.
// ---------------------------------------------------------------------------
__device__ __forceinline__ int idx_w(float c) {
    float v = __fmul_rn(__fadd_rn(c, 1.0f), 63.5f);     // 0.5*(128-1) folded
    int k = (int)rintf(v);
    return min(max(k, 0), RES_W - 1);
}
__device__ __forceinline__ int idx_h(float c) {
    float v = __fmul_rn(__fadd_rn(c, 1.0f), 255.5f);    // 0.5*(512-1) folded
    int k = (int)rintf(v);
    return min(max(k, 0), RES_H - 1);
}

__device__ __forceinline__ int plane_base(const float* __restrict__ pts,
                                          const float* __restrict__ tim,
                                          int li, int ix, int axis) {
    const float p = __fmul_rn(-pts[3 * li + axis], INV_BOUNDS_F);
    return (idx_h(p) * RES_W + ix) * FEAT;
}

// ---------------------------------------------------------------------------
// Main kernel: warp handles PPW=16 points.
// Phase 1: lanes 0..15 compute the 3 plane base offsets of one point each.
// Phase 2: 4 iterations; each handles 4 points (group g=lane>>3 -> point,
//          lane&7 -> float4 feature chunk): 3 shfl + 3 LDG.128 + 4 f32x2
//          muls + 2 STG.128 per quad. feat written to BOTH outputs; the
//          last-point special case is fixed up by a separate kernel.
// ---------------------------------------------------------------------------
__global__ void displacement_kernel(const float* __restrict__ pts,
                                    const float* __restrict__ tim,
                                    float* __restrict__ out,
                                    int n) {
    const int warp_id = blockIdx.x * (blockDim.x >> 5) + (threadIdx.x >> 5);
    const int lane = threadIdx.x & 31;
    const int base = warp_id * PPW;
    if (base >= n) return;

    // Phase 1
    int b0 = 0, b1 = 0, b2 = 0;
    const int li = base + lane;
    if (lane < PPW && li < n) {
        const float t = __fadd_rn(__fmul_rn(tim[li], 2.0f), -1.0f);
        const int ix = idx_w(t);
        b0 = plane_base(pts, tim, li, ix, 0);
        b1 = plane_base(pts, tim, li, ix, 1);
        b2 = plane_base(pts, tim, li, ix, 2);
    }

    const int g  = lane >> 3;          // point within quad
    const int fe = (lane & 7) * 4;     // feature chunk
    const long long nb = (long long)n * FEAT;

    // Phase 2
    #pragma unroll
    for (int j = 0; j < PPW / 4; j++) {
        const int src = j * 4 + g;                 // phase-1 lane holding my point
        const int i = base + src;                  // my point index
        const int o0 = __shfl_sync(0xffffffffu, b0, src) + fe;
        const int o1 = __shfl_sync(0xffffffffu, b1, src) + fe;
        const int o2 = __shfl_sync(0xffffffffu, b2, src) + fe;
        if (i < n) {
            const ulonglong2 a = *(const ulonglong2*)&g_tp[0][o0];
            const ulonglong2 b = *(const ulonglong2*)&g_tp[1][o1];
            const ulonglong2 c = *(const ulonglong2*)&g_tp[2][o2];
            ulonglong2 r;
            r.x = mul2(mul2(a.x, b.x), c.x);
            r.y = mul2(mul2(a.y, b.y), c.y);
            *(ulonglong2*)&out[(long long)i * FEAT + fe] = r;       // feature_A
            *(ulonglong2*)&out[nb + (long long)i * FEAT + fe] = r;  // feature_B
        }
    }
}

// ---------------------------------------------------------------------------
// Fixup: recompute point n-1 with orig + shifted coords and the scalar cond
// select; overwrite its two output rows. One warp, lane = feature.
// ---------------------------------------------------------------------------
__global__ void fixup_last(const float* __restrict__ pts,
                           const float* __restrict__ tim,
                           float* __restrict__ out,
                           int n) {
    const int lane = threadIdx.x;      // 0..31
    const int i = n - 1;

    const float t  = __fadd_rn(__fmul_rn(tim[i], 2.0f), -1.0f);
    const float p0 = __fmul_rn(-pts[3 * i + 0], INV_BOUNDS_F);
    const float p1 = __fmul_rn(-pts[3 * i + 1], INV_BOUNDS_F);
    const float p2 = __fmul_rn(-pts[3 * i + 2], INV_BOUNDS_F);

    const int ix = idx_w(t);
    const float fo = __fmul_rn(__fmul_rn(
        __ldg(&g_tp[0][(idx_h(p0) * RES_W + ix) * FEAT + lane]),
        __ldg(&g_tp[1][(idx_h(p1) * RES_W + ix) * FEAT + lane])),
        __ldg(&g_tp[2][(idx_h(p2) * RES_W + ix) * FEAT + lane]));

    // data.at[-1].add(-TIME_STEP): all 4 coords of the last row shift.
    const float ts = __fadd_rn(t,  -TIME_STEP_F);
    const float q0 = __fadd_rn(p0, -TIME_STEP_F);
    const float q1 = __fadd_rn(p1, -TIME_STEP_F);
    const float q2 = __fadd_rn(p2, -TIME_STEP_F);
    const int ixs = idx_w(ts);
    const float fs = __fmul_rn(__fmul_rn(
        __ldg(&g_tp[0][(idx_h(q0) * RES_W + ixs) * FEAT + lane]),
        __ldg(&g_tp[1][(idx_h(q1) * RES_W + ixs) * FEAT + lane])),
        __ldg(&g_tp[2][(idx_h(q2) * RES_W + ixs) * FEAT + lane]));

    const bool cond = __fadd_rn(p0, TIME_STEP_F) > 1.0f;
    const float fa = cond ? fs : fo;
    const float fb = cond ? fo : fs;

    out[(long long)i * FEAT + lane] = fa;
    out[(long long)n * FEAT + (long long)i * FEAT + lane] = fb;
}

extern "C" void kernel_launch(void* const* d_in, const int* in_sizes, int n_in,
                              void* d_out, int out_size) {
    const float* pts    = (const float*)d_in[0];
    const float* tim    = (const float*)d_in[1];
    const float* plane0 = (const float*)d_in[2];
    const float* plane1 = (const float*)d_in[3];
    const float* plane2 = (const float*)d_in[4];
    float* out = (float*)d_out;

    const int n = in_sizes[0] / 3;   // pts is [N,3]

    // 1) Transpose planes into [H,W,F] scratch (float4 both sides).
    dim3 tg(HW / 128, 3);
    transpose_planes<<<tg, 256>>>(plane0, plane1, plane2);

    // 2) Main gather-product-store: 16 points per warp.
    const int block = 256;                         // 8 warps
    const int pts_per_block = (block / 32) * PPW;  // 128
    const int grid = (n + pts_per_block - 1) / pts_per_block;
    displacement_kernel<<<grid, block>>>(pts, tim, out, n);

    // 3) Last-point shifted/cond fixup.
    fixup_last<<<1, 32>>>(pts, tim, out, n);
}

// round 6
// speedup vs baseline: 2.8289x; 1.4862x over previous
#include <cuda_runtime.h>

#define FEAT 32
#define RES_H 512
#define RES_W 128
#define HW (RES_H * RES_W)
#define PLANE_ELEMS (FEAT * HW)
#define TIME_STEP_F 0.00390625f   /* 1/(2*128), exact in fp32 */
#define INV_BOUNDS_F 0.625f       /* fp32(1/fp32(1.6)) == 0.625 exactly (XLA folds /1.6 -> *0.625) */
#define PPW 32                    /* points per warp */

// 3 transposed planes, layout [H][W][F]: 32 features contiguous (one 128B line).
__device__ float g_tp[3][PLANE_ELEMS];

// Packed f32 pair multiply (sm_103a) — IEEE rn per element, bit-identical to
// two scalar __fmul_rn.
__device__ __forceinline__ unsigned long long mul2(unsigned long long a,
                                                   unsigned long long b) {
    unsigned long long r;
    asm("mul.rn.f32x2 %0, %1, %2;" : "=l"(r) : "l"(a), "l"(b));
    return r;
}

// ---------------------------------------------------------------------------
// Pre-pass: transpose [F=32, HW] -> [HW, F]. Tile = 256 hw x 32 f per block,
// 8 float4 loads + 8 float4 stores per thread (deep MLP, 32KB in/out per
// block). Both global sides fully coalesced (512B per warp per access).
// ---------------------------------------------------------------------------
__global__ void transpose_planes(const float* __restrict__ p0,
                                 const float* __restrict__ p1,
                                 const float* __restrict__ p2) {
    __shared__ float tile[256][33];     // [hw][f], +1 pad
    const int plane = blockIdx.y;
    const float* __restrict__ src = (plane == 0) ? p0 : ((plane == 1) ? p1 : p2);
    float* __restrict__ dst = g_tp[plane];

    const int hw0 = blockIdx.x * 256;
    const int tid = threadIdx.x;

    #pragma unroll
    for (int k = 0; k < 8; k++) {
        const int lin = tid + 256 * k;      // 0..2047
        const int f  = lin >> 6;            // 0..31
        const int vc = lin & 63;            // float4 column within 256 hw
        const float4 v = *(const float4*)&src[f * HW + hw0 + vc * 4];
        tile[vc * 4 + 0][f] = v.x;
        tile[vc * 4 + 1][f] = v.y;
        tile[vc * 4 + 2][f] = v.z;
        tile[vc * 4 + 3][f] = v.w;
    }
    __syncthreads();
    #pragma unroll
    for (int k = 0; k < 8; k++) {
        const int lin = tid + 256 * k;      // 0..2047
        const int r  = lin >> 3;            // 0..255 (hw row)
        const int fc = lin & 7;             // float4 chunk of features
        float4 w;
        w.x = tile[r][fc * 4 + 0];
        w.y = tile[r][fc * 4 + 1];
        w.z = tile[r][fc * 4 + 2];
        w.w = tile[r][fc * 4 + 3];
        *(float4*)&dst[(hw0 + r) * FEAT + fc * 4] = w;
    }
}

// ---------------------------------------------------------------------------
// Index math — XLA-folded forms, round half-to-even, clamp. No FMA contraction.
// ---------------------------------------------------------------------------
__device__ __forceinline__ int idx_w(float c) {
    float v = __fmul_rn(__fadd_rn(c, 1.0f), 63.5f);     // 0.5*(128-1) folded
    int k = (int)rintf(v);
    return min(max(k, 0), RES_W - 1);
}
__device__ __forceinline__ int idx_h(float c) {
    float v = __fmul_rn(__fadd_rn(c, 1.0f), 255.5f);    // 0.5*(512-1) folded
    int k = (int)rintf(v);
    return min(max(k, 0), RES_H - 1);
}

// ---------------------------------------------------------------------------
// Main kernel: warp handles PPW=32 points.
// Phase 1: every lane computes the 3 plane base offsets of one point.
// Phase 2: 8 unrolled iterations; each handles 4 points (g=lane>>3 -> point,
//          lane&7 -> float4 chunk): 3 shfl + 3 LDG.128 + packed muls +
//          2 streaming STG.128. Point n-1 is skipped here and handled by
//          warp 0's fused fixup (disjoint rows -> race-free).
// ---------------------------------------------------------------------------
__global__ void displacement_kernel(const float* __restrict__ pts,
                                    const float* __restrict__ tim,
                                    float* __restrict__ out,
                                    int n) {
    const int warp_id = blockIdx.x * (blockDim.x >> 5) + (threadIdx.x >> 5);
    const int lane = threadIdx.x & 31;
    const long long nb = (long long)n * FEAT;

    // ---- Fused last-point fixup (warp 0 only; writes rows for i = n-1) ----
    if (warp_id == 0) {
        const int i = n - 1;
        const float t  = __fadd_rn(__fmul_rn(tim[i], 2.0f), -1.0f);
        const float p0 = __fmul_rn(-pts[3 * i + 0], INV_BOUNDS_F);
        const float p1 = __fmul_rn(-pts[3 * i + 1], INV_BOUNDS_F);
        const float p2 = __fmul_rn(-pts[3 * i + 2], INV_BOUNDS_F);
        const int ix = idx_w(t);
        const float fo = __fmul_rn(__fmul_rn(
            __ldg(&g_tp[0][(idx_h(p0) * RES_W + ix) * FEAT + lane]),
            __ldg(&g_tp[1][(idx_h(p1) * RES_W + ix) * FEAT + lane])),
            __ldg(&g_tp[2][(idx_h(p2) * RES_W + ix) * FEAT + lane]));
        // data.at[-1].add(-TIME_STEP): all 4 coords of the last row shift.
        const float ts = __fadd_rn(t,  -TIME_STEP_F);
        const float q0 = __fadd_rn(p0, -TIME_STEP_F);
        const float q1 = __fadd_rn(p1, -TIME_STEP_F);
        const float q2 = __fadd_rn(p2, -TIME_STEP_F);
        const int ixs = idx_w(ts);
        const float fs = __fmul_rn(__fmul_rn(
            __ldg(&g_tp[0][(idx_h(q0) * RES_W + ixs) * FEAT + lane]),
            __ldg(&g_tp[1][(idx_h(q1) * RES_W + ixs) * FEAT + lane])),
            __ldg(&g_tp[2][(idx_h(q2) * RES_W + ixs) * FEAT + lane]));
        const bool cond = __fadd_rn(p0, TIME_STEP_F) > 1.0f;
        out[(long long)i * FEAT + lane]      = cond ? fs : fo;   // feature_A
        out[nb + (long long)i * FEAT + lane] = cond ? fo : fs;   // feature_B
    }

    const int base = warp_id * PPW;
    if (base >= n) return;

    // Phase 1: one point per lane.
    int b0 = 0, b1 = 0, b2 = 0;
    const int li = base + lane;
    if (li < n) {
        const float t  = __fadd_rn(__fmul_rn(tim[li], 2.0f), -1.0f);
        const float p0 = __fmul_rn(-pts[3 * li + 0], INV_BOUNDS_F);
        const float p1 = __fmul_rn(-pts[3 * li + 1], INV_BOUNDS_F);
        const float p2 = __fmul_rn(-pts[3 * li + 2], INV_BOUNDS_F);
        const int ix = idx_w(t);
        b0 = (idx_h(p0) * RES_W + ix) * FEAT;
        b1 = (idx_h(p1) * RES_W + ix) * FEAT;
        b2 = (idx_h(p2) * RES_W + ix) * FEAT;
    }

    const int g  = lane >> 3;          // point within quad
    const int fe = (lane & 7) * 4;     // feature chunk
    const int n_main = n - 1;          // point n-1 handled by fixup

    // Phase 2
    #pragma unroll
    for (int j = 0; j < PPW / 4; j++) {
        const int src = j * 4 + g;
        const int i = base + src;
        const int o0 = __shfl_sync(0xffffffffu, b0, src) + fe;
        const int o1 = __shfl_sync(0xffffffffu, b1, src) + fe;
        const int o2 = __shfl_sync(0xffffffffu, b2, src) + fe;
        if (i < n_main) {
            const ulonglong2 a = *(const ulonglong2*)&g_tp[0][o0];
            const ulonglong2 b = *(const ulonglong2*)&g_tp[1][o1];
            const ulonglong2 c = *(const ulonglong2*)&g_tp[2][o2];
            float4 r;
            ulonglong2 rr;
            rr.x = mul2(mul2(a.x, b.x), c.x);
            rr.y = mul2(mul2(a.y, b.y), c.y);
            r = *(float4*)&rr;
            // Streaming stores: write-once data, evict-first (keep planes hot).
            __stcs((float4*)&out[(long long)i * FEAT + fe], r);        // A
            __stcs((float4*)&out[nb + (long long)i * FEAT + fe], r);   // B
        }
    }
}

extern "C" void kernel_launch(void* const* d_in, const int* in_sizes, int n_in,
                              void* d_out, int out_size) {
    const float* pts    = (const float*)d_in[0];
    const float* tim    = (const float*)d_in[1];
    const float* plane0 = (const float*)d_in[2];
    const float* plane1 = (const float*)d_in[3];
    const float* plane2 = (const float*)d_in[4];
    float* out = (float*)d_out;

    const int n = in_sizes[0] / 3;   // pts is [N,3]

    // 1) Transpose planes into [H,W,F] scratch (256-hw tiles, MLP=8).
    dim3 tg(HW / 256, 3);
    transpose_planes<<<tg, 256>>>(plane0, plane1, plane2);

    // 2) Main gather-product-store (fixup fused): 32 points per warp.
    const int block = 256;                         // 8 warps
    const int pts_per_block = (block / 32) * PPW;  // 256
    const int grid = (n + pts_per_block - 1) / pts_per_block;
    displacement_kernel<<<grid, block>>>(pts, tim, out, n);
}